// round 10
// baseline (speedup 1.0000x reference)
#include <cuda_runtime.h>
#include <cuda_fp16.h>

// BilateralSliceApply on GB300 — Round 9.
// grid (4,16,16,8,12) f32, guide (4,1024,1024), inp/out (4,1024,1024,3).
//
// All R4-R8 variants converge at kernel ~26us (floors: LDS ~12, fma ~12,
// DRAM ~17 -> ideal ~17-18). Residual matches B300 cross-CTA L1tex-queue
// contention from front-batched stage LDGs. R9: 8 rows per block with
// DOUBLE-BUFFERED PY staging — row r+1 staged while row r computes, so
// stage LDG latency is hidden and LDG bursts are spread through time.
// Inner loop = R4's conflict-free 3xLDS.64 + HFMA2 form, verbatim.

#define GH 16
#define GW 16
#define GD 8
#define HH 1024
#define WW 1024
#define TPB 256
#define NXS 18                 // 16 x cells + halo each side (xbase = -1)
#define RPB 8                  // rows per block
#define PLANE3 (NXS * GD * 3)  // 432 uint2 per row plane

__device__ __forceinline__ __half2 u2h(unsigned v) {
    __half2 h; asm("mov.b32 %0, %1;" : "=r"(*(unsigned*)&h) : "r"(v)); return h;
}

// Stage one row's fp16 y-interpolated plane into dst (cooperative, no barrier).
__device__ __forceinline__ void stage_row(
    uint2* __restrict__ dst, const float* __restrict__ grid,
    int b, int y, int tid)
{
    const int vy = 2 * y - 63;
    const int fy = vy >> 7;
    const float wy1 = (float)(vy & 127) * (1.0f / 128.0f);
    const float wy0 = 1.0f - wy1;
    const int cy0 = min(max(fy,     0), GH - 1);
    const int cy1 = min(max(fy + 1, 0), GH - 1);

    #pragma unroll
    for (int e = tid; e < PLANE3; e += TPB) {
        const int c4 = e % 3;
        int q = e / 3;
        const int z  = q & (GD - 1);
        const int xi = q >> 3;
        const int gx = min(max(xi - 1, 0), GW - 1);

        const float4* g0 = reinterpret_cast<const float4*>(grid)
            + (size_t)(((b * GH + cy0) * GW + gx) * GD + z) * 3 + c4;
        const float4* g1 = reinterpret_cast<const float4*>(grid)
            + (size_t)(((b * GH + cy1) * GW + gx) * GD + z) * 3 + c4;
        const float4 a  = __ldg(g0);
        const float4 bb = __ldg(g1);
        const __half2 h0 = __floats2half2_rn(wy0 * a.x + wy1 * bb.x,
                                             wy0 * a.y + wy1 * bb.y);
        const __half2 h1 = __floats2half2_rn(wy0 * a.z + wy1 * bb.z,
                                             wy0 * a.w + wy1 * bb.w);
        uint2 v;
        v.x = *(const unsigned*)&h0;
        v.y = *(const unsigned*)&h1;
        dst[e] = v;
    }
}

__global__ void __launch_bounds__(TPB) bsa_kernel(
    const float* __restrict__ grid,
    const float* __restrict__ guide,
    const float* __restrict__ inp,
    float* __restrict__ out)
{
    __shared__ uint2 PY[2][PLANE3];     // double buffer, 6.75 KB total

    const int y0  = blockIdx.x * RPB;
    const int b   = blockIdx.y;
    const int tid = threadIdx.x;
    const int x0  = tid * 4;

    // prefetch row 0 pixel data
    const size_t row0 = (size_t)(b * HH + y0) * WW;
    float4 g4n = __ldg(reinterpret_cast<const float4*>(guide + row0) + tid);
    const float4* ib0 = reinterpret_cast<const float4*>(inp + row0 * 3);
    float4 ian = __ldg(ib0 + tid * 3 + 0);
    float4 ibn = __ldg(ib0 + tid * 3 + 1);
    float4 icn = __ldg(ib0 + tid * 3 + 2);

    // stage row 0 plane into buffer 0
    stage_row(PY[0], grid, b, y0, tid);
    __syncthreads();

    // x taps: cell uniform over the thread's 4 px, row-invariant
    const int vx = 2 * x0 - 63;
    const int fx = vx >> 7;
    const float wx1base = (float)(vx & 127) * (1.0f / 128.0f);
    const int ebr = (fx + 1) * (GD * 3);   // x-cell base (uint2 units)

    #pragma unroll 1
    for (int r = 0; r < RPB; r++) {
        // consume prefetched pixel data
        const float4 g4 = g4n;
        const float4 ia = ian;
        const float4 ib = ibn;
        const float4 ic = icn;

        if (r + 1 < RPB) {
            // prefetch next row pixel data
            const size_t rn = (size_t)(b * HH + y0 + r + 1) * WW;
            g4n = __ldg(reinterpret_cast<const float4*>(guide + rn) + tid);
            const float4* ibp = reinterpret_cast<const float4*>(inp + rn * 3);
            ian = __ldg(ibp + tid * 3 + 0);
            ibn = __ldg(ibp + tid * 3 + 1);
            icn = __ldg(ibp + tid * 3 + 2);
            // stage next row plane into the other buffer (overlaps compute)
            stage_row(PY[(r + 1) & 1], grid, b, y0 + r + 1, tid);
        }

        const uint2* __restrict__ cur = PY[r & 1];
        const int ebase0 = ebr;
        const int ebase1 = ebr + GD * 3;
        const float gin[4] = {g4.x, g4.y, g4.z, g4.w};
        float o[12];

        #pragma unroll
        for (int p = 0; p < 4; p++) {
            const float wx1 = wx1base + (float)p * (2.0f / 128.0f);
            const float wx0 = 1.0f - wx1;

            const float tz = fmaf(gin[p], (float)GD, -0.5f);
            const float fz = floorf(tz);
            const float wz1 = tz - fz;
            const float wz0 = 1.0f - wz1;
            const int iz = (int)fz;
            const int z0 = min(max(iz,     0), GD - 1);
            const int z1 = min(max(iz + 1, 0), GD - 1);

            const __half2 W00 = __float2half2_rn(wx0 * wz0);
            const __half2 W01 = __float2half2_rn(wx0 * wz1);
            const __half2 W10 = __float2half2_rn(wx1 * wz0);
            const __half2 W11 = __float2half2_rn(wx1 * wz1);

            const int e00 = ebase0 + z0 * 3;
            const int e01 = ebase0 + z1 * 3;
            const int e10 = ebase1 + z0 * 3;
            const int e11 = ebase1 + z1 * 3;

            __half2 a0 = __float2half2_rn(0.f), a1 = a0, a2 = a0,
                    a3 = a0, a4 = a0, a5 = a0;
            {
                const uint2 q0 = cur[e00], q1 = cur[e00 + 1], q2 = cur[e00 + 2];
                a0 = __hfma2(u2h(q0.x), W00, a0); a1 = __hfma2(u2h(q0.y), W00, a1);
                a2 = __hfma2(u2h(q1.x), W00, a2); a3 = __hfma2(u2h(q1.y), W00, a3);
                a4 = __hfma2(u2h(q2.x), W00, a4); a5 = __hfma2(u2h(q2.y), W00, a5);
            }
            {
                const uint2 q0 = cur[e01], q1 = cur[e01 + 1], q2 = cur[e01 + 2];
                a0 = __hfma2(u2h(q0.x), W01, a0); a1 = __hfma2(u2h(q0.y), W01, a1);
                a2 = __hfma2(u2h(q1.x), W01, a2); a3 = __hfma2(u2h(q1.y), W01, a3);
                a4 = __hfma2(u2h(q2.x), W01, a4); a5 = __hfma2(u2h(q2.y), W01, a5);
            }
            {
                const uint2 q0 = cur[e10], q1 = cur[e10 + 1], q2 = cur[e10 + 2];
                a0 = __hfma2(u2h(q0.x), W10, a0); a1 = __hfma2(u2h(q0.y), W10, a1);
                a2 = __hfma2(u2h(q1.x), W10, a2); a3 = __hfma2(u2h(q1.y), W10, a3);
                a4 = __hfma2(u2h(q2.x), W10, a4); a5 = __hfma2(u2h(q2.y), W10, a5);
            }
            {
                const uint2 q0 = cur[e11], q1 = cur[e11 + 1], q2 = cur[e11 + 2];
                a0 = __hfma2(u2h(q0.x), W11, a0); a1 = __hfma2(u2h(q0.y), W11, a1);
                a2 = __hfma2(u2h(q1.x), W11, a2); a3 = __hfma2(u2h(q1.y), W11, a3);
                a4 = __hfma2(u2h(q2.x), W11, a4); a5 = __hfma2(u2h(q2.y), W11, a5);
            }

            const float c0 = __low2float(a0), c1 = __high2float(a0);
            const float c2 = __low2float(a1), c3 = __high2float(a1);
            const float c4 = __low2float(a2), c5 = __high2float(a2);
            const float c6 = __low2float(a3), c7 = __high2float(a3);
            const float c8 = __low2float(a4), c9 = __high2float(a4);
            const float cA = __low2float(a5), cB = __high2float(a5);

            float i0, i1, i2;
            if (p == 0)      { i0 = ia.x; i1 = ia.y; i2 = ia.z; }
            else if (p == 1) { i0 = ia.w; i1 = ib.x; i2 = ib.y; }
            else if (p == 2) { i0 = ib.z; i1 = ib.w; i2 = ic.x; }
            else             { i0 = ic.y; i1 = ic.z; i2 = ic.w; }

            o[3 * p + 0] = c0 * i0 + c1 * i1 + c2 * i2 + c3;
            o[3 * p + 1] = c4 * i0 + c5 * i1 + c6 * i2 + c7;
            o[3 * p + 2] = c8 * i0 + c9 * i1 + cA * i2 + cB;
        }

        // batched epilogue stores for this row
        float4* obase = reinterpret_cast<float4*>(
            out + (size_t)(b * HH + y0 + r) * WW * 3);
        obase[tid * 3 + 0] = make_float4(o[0], o[1], o[2],  o[3]);
        obase[tid * 3 + 1] = make_float4(o[4], o[5], o[6],  o[7]);
        obase[tid * 3 + 2] = make_float4(o[8], o[9], o[10], o[11]);

        // protects: (a) next row's buffer fully staged before reads,
        // (b) no warp re-stages over a buffer still being read.
        __syncthreads();
    }
}

extern "C" void kernel_launch(void* const* d_in, const int* in_sizes, int n_in,
                              void* d_out, int out_size)
{
    const float* grid  = (const float*)d_in[0];
    const float* guide = (const float*)d_in[1];
    const float* inp   = (const float*)d_in[2];
    float* out = (float*)d_out;

    const int B = in_sizes[1] / (HH * WW);  // 4

    dim3 blk(TPB, 1, 1);
    dim3 grd(HH / RPB, B, 1);               // (128, 4)
    bsa_kernel<<<grd, blk>>>(grid, guide, inp, out);
}

// round 11
// speedup vs baseline: 1.1231x; 1.1231x over previous
#include <cuda_runtime.h>
#include <cuda_fp16.h>

// BilateralSliceApply on GB300 — Round 10.
// grid (4,16,16,8,12) f32, guide (4,1024,1024), inp/out (4,1024,1024,3).
//
// Shell = R4 (measured best): one block per row, 256 thr x 4 px, fp16 PY
// plane (y-interp hoisted), conflict-free 3xLDS.64 taps, batched .128 I/O.
// R10 deltas: (1) split accumulation into two depth-2 HFMA2 trees (x0/x1)
// merged by HADD2 (serial depth 5->3), (2) pair-hoisted z-setup,
// (3) trimmed z clamps (iz in [-1,7] -> one-sided clamps).

#define GH 16
#define GW 16
#define GD 8
#define HH 1024
#define WW 1024
#define TPB 256
#define NXS 18               // 16 x cells + halo each side (xbase = -1)

__device__ __forceinline__ __half2 u2h(unsigned v) {
    __half2 h; asm("mov.b32 %0, %1;" : "=r"(*(unsigned*)&h) : "r"(v)); return h;
}

__global__ void __launch_bounds__(TPB) bsa_kernel(
    const float* __restrict__ grid,
    const float* __restrict__ guide,
    const float* __restrict__ inp,
    float* __restrict__ out)
{
    // [xi(18)][z(8)][c12] fp16 = 3.375 KB, uint2 entries (3 per z-row)
    __shared__ uint2 PY[NXS * GD * 3];

    const int y   = blockIdx.x;
    const int b   = blockIdx.y;
    const int tid = threadIdx.x;
    const int x0  = tid * 4;

    // early global loads
    const size_t rowpix = (size_t)(b * HH + y) * WW;
    const float4 g4 = __ldg(reinterpret_cast<const float4*>(guide + rowpix) + tid);
    const float4* ibase = reinterpret_cast<const float4*>(inp + rowpix * 3);
    const float4 ia = __ldg(ibase + tid * 3 + 0);
    const float4 ib = __ldg(ibase + tid * 3 + 1);
    const float4 ic = __ldg(ibase + tid * 3 + 2);

    // y taps (uniform over row): gy - 0.5 = (2y-63)/128
    const int vy = 2 * y - 63;
    const int fy = vy >> 7;
    const float wy1 = (float)(vy & 127) * (1.0f / 128.0f);
    const float wy0 = 1.0f - wy1;
    const int cy0 = min(max(fy,     0), GH - 1);
    const int cy1 = min(max(fy + 1, 0), GH - 1);

    // stage PY = fp16(wy0*grid[cy0] + wy1*grid[cy1]): 432 entries
    #pragma unroll
    for (int e = tid; e < NXS * GD * 3; e += TPB) {
        const int c4 = e % 3;
        const int z  = (e / 3) & (GD - 1);
        const int xi = e / (3 * GD);
        const int gx = min(max(xi - 1, 0), GW - 1);
        const float4* g0 = reinterpret_cast<const float4*>(grid)
            + (size_t)(((b * GH + cy0) * GW + gx) * GD + z) * 3 + c4;
        const float4* g1 = reinterpret_cast<const float4*>(grid)
            + (size_t)(((b * GH + cy1) * GW + gx) * GD + z) * 3 + c4;
        const float4 a  = __ldg(g0);
        const float4 bb = __ldg(g1);
        const __half2 h0 = __floats2half2_rn(wy0 * a.x + wy1 * bb.x,
                                             wy0 * a.y + wy1 * bb.y);
        const __half2 h1 = __floats2half2_rn(wy0 * a.z + wy1 * bb.z,
                                             wy0 * a.w + wy1 * bb.w);
        uint2 v;
        v.x = *(const unsigned*)&h0;
        v.y = *(const unsigned*)&h1;
        PY[e] = v;
    }
    __syncthreads();

    // x taps: cell uniform over the thread's 4 px
    const int vx = 2 * x0 - 63;
    const int fx = vx >> 7;
    const float wx1base = (float)(vx & 127) * (1.0f / 128.0f);
    const int ebase0 = (fx + 1) * (GD * 3);
    const int ebase1 = ebase0 + GD * 3;

    const float gin[4] = {g4.x, g4.y, g4.z, g4.w};
    float o[12];

    #pragma unroll
    for (int pp = 0; pp < 4; pp += 2) {
        // ---- hoisted z-setup + weights for the pair ----
        int e00[2], e01[2], e10[2], e11[2];
        __half2 W00[2], W01[2], W10[2], W11[2];
        #pragma unroll
        for (int q = 0; q < 2; q++) {
            const int p = pp + q;
            const float wx1 = wx1base + (float)p * (2.0f / 128.0f);
            const float wx0 = 1.0f - wx1;
            // tz in [-0.5, 7.5] -> iz in [-1, 7]: one-sided clamps suffice
            const float tz = fmaf(gin[p], (float)GD, -0.5f);
            const int iz = __float2int_rd(tz);
            const float wz1 = tz - (float)iz;
            const float wz0 = 1.0f - wz1;
            const int z0 = max(iz, 0);
            const int z1 = min(iz + 1, GD - 1);
            e00[q] = ebase0 + z0 * 3;  e01[q] = ebase0 + z1 * 3;
            e10[q] = ebase1 + z0 * 3;  e11[q] = ebase1 + z1 * 3;
            W00[q] = __float2half2_rn(wx0 * wz0);
            W01[q] = __float2half2_rn(wx0 * wz1);
            W10[q] = __float2half2_rn(wx1 * wz0);
            W11[q] = __float2half2_rn(wx1 * wz1);
        }

        #pragma unroll
        for (int q = 0; q < 2; q++) {
            const int p = pp + q;

            // tree A: x0 taps (depth 2)
            const uint2 qa0 = PY[e00[q]], qa1 = PY[e00[q] + 1], qa2 = PY[e00[q] + 2];
            __half2 A0 = __hmul2(u2h(qa0.x), W00[q]);
            __half2 A1 = __hmul2(u2h(qa0.y), W00[q]);
            __half2 A2 = __hmul2(u2h(qa1.x), W00[q]);
            __half2 A3 = __hmul2(u2h(qa1.y), W00[q]);
            __half2 A4 = __hmul2(u2h(qa2.x), W00[q]);
            __half2 A5 = __hmul2(u2h(qa2.y), W00[q]);
            const uint2 qb0 = PY[e01[q]], qb1 = PY[e01[q] + 1], qb2 = PY[e01[q] + 2];
            A0 = __hfma2(u2h(qb0.x), W01[q], A0);
            A1 = __hfma2(u2h(qb0.y), W01[q], A1);
            A2 = __hfma2(u2h(qb1.x), W01[q], A2);
            A3 = __hfma2(u2h(qb1.y), W01[q], A3);
            A4 = __hfma2(u2h(qb2.x), W01[q], A4);
            A5 = __hfma2(u2h(qb2.y), W01[q], A5);

            // tree B: x1 taps (depth 2, independent of tree A)
            const uint2 qc0 = PY[e10[q]], qc1 = PY[e10[q] + 1], qc2 = PY[e10[q] + 2];
            __half2 B0 = __hmul2(u2h(qc0.x), W10[q]);
            __half2 B1 = __hmul2(u2h(qc0.y), W10[q]);
            __half2 B2 = __hmul2(u2h(qc1.x), W10[q]);
            __half2 B3 = __hmul2(u2h(qc1.y), W10[q]);
            __half2 B4 = __hmul2(u2h(qc2.x), W10[q]);
            __half2 B5 = __hmul2(u2h(qc2.y), W10[q]);
            const uint2 qd0 = PY[e11[q]], qd1 = PY[e11[q] + 1], qd2 = PY[e11[q] + 2];
            B0 = __hfma2(u2h(qd0.x), W11[q], B0);
            B1 = __hfma2(u2h(qd0.y), W11[q], B1);
            B2 = __hfma2(u2h(qd1.x), W11[q], B2);
            B3 = __hfma2(u2h(qd1.y), W11[q], B3);
            B4 = __hfma2(u2h(qd2.x), W11[q], B4);
            B5 = __hfma2(u2h(qd2.y), W11[q], B5);

            // merge trees
            const __half2 a0 = __hadd2(A0, B0);
            const __half2 a1 = __hadd2(A1, B1);
            const __half2 a2 = __hadd2(A2, B2);
            const __half2 a3 = __hadd2(A3, B3);
            const __half2 a4 = __hadd2(A4, B4);
            const __half2 a5 = __hadd2(A5, B5);

            const float c0 = __low2float(a0), c1 = __high2float(a0);
            const float c2 = __low2float(a1), c3 = __high2float(a1);
            const float c4 = __low2float(a2), c5 = __high2float(a2);
            const float c6 = __low2float(a3), c7 = __high2float(a3);
            const float c8 = __low2float(a4), c9 = __high2float(a4);
            const float cA = __low2float(a5), cB = __high2float(a5);

            float i0, i1, i2;
            if (p == 0)      { i0 = ia.x; i1 = ia.y; i2 = ia.z; }
            else if (p == 1) { i0 = ia.w; i1 = ib.x; i2 = ib.y; }
            else if (p == 2) { i0 = ib.z; i1 = ib.w; i2 = ic.x; }
            else             { i0 = ic.y; i1 = ic.z; i2 = ic.w; }

            o[3 * p + 0] = c0 * i0 + c1 * i1 + c2 * i2 + c3;
            o[3 * p + 1] = c4 * i0 + c5 * i1 + c6 * i2 + c7;
            o[3 * p + 2] = c8 * i0 + c9 * i1 + cA * i2 + cB;
        }
    }

    // batched epilogue stores
    float4* obase = reinterpret_cast<float4*>(out + rowpix * 3);
    obase[tid * 3 + 0] = make_float4(o[0], o[1], o[2],  o[3]);
    obase[tid * 3 + 1] = make_float4(o[4], o[5], o[6],  o[7]);
    obase[tid * 3 + 2] = make_float4(o[8], o[9], o[10], o[11]);
}

extern "C" void kernel_launch(void* const* d_in, const int* in_sizes, int n_in,
                              void* d_out, int out_size)
{
    const float* grid  = (const float*)d_in[0];
    const float* guide = (const float*)d_in[1];
    const float* inp   = (const float*)d_in[2];
    float* out = (float*)d_out;

    const int B = in_sizes[1] / (HH * WW);  // 4

    dim3 blk(TPB, 1, 1);
    dim3 grd(HH, B, 1);                     // one block per image row
    bsa_kernel<<<grd, blk>>>(grid, guide, inp, out);
}

// round 13
// speedup vs baseline: 1.2172x; 1.0838x over previous
#include <cuda_runtime.h>
#include <cuda_fp16.h>

// BilateralSliceApply on GB300 — Round 12 (R11 rerun; container infra failed).
// grid (4,16,16,8,12) f32, guide (4,1024,1024), inp/out (4,1024,1024,3).
//
// Body = R10 (best measured: split depth-2 HFMA2 trees merged by HADD2,
// pair-hoisted z-setup, one-sided z clamps, conflict-free 3xLDS.64 taps,
// batched .128 pixel I/O). Deltas under test:
//   (1) __launch_bounds__(256, 6): occupancy 5->6 blocks/SM on this body
//   (2) RPB=2: two rows per block, one stage+barrier per 2 rows
// (R11's packed-f32x2 apply dropped: unmeasured, thin paper margin,
//  longer dependency chain.)

#define GH 16
#define GW 16
#define GD 8
#define HH 1024
#define WW 1024
#define TPB 256
#define NXS 18               // 16 x cells + halo each side (xbase = -1)
#define RPB 2                // rows per block (sequential)
#define PLANE3 (NXS * GD * 3)

__device__ __forceinline__ __half2 u2h(unsigned v) {
    __half2 h; asm("mov.b32 %0, %1;" : "=r"(*(unsigned*)&h) : "r"(v)); return h;
}

__global__ void __launch_bounds__(TPB, 6) bsa_kernel(
    const float* __restrict__ grid,
    const float* __restrict__ guide,
    const float* __restrict__ inp,
    float* __restrict__ out)
{
    __shared__ uint2 PY[RPB * PLANE3];   // 6.75 KB, [r][xi][z][c4] fp16

    const int y0  = blockIdx.x * RPB;
    const int b   = blockIdx.y;
    const int tid = threadIdx.x;
    const int x0  = tid * 4;

    // x taps: cell uniform over the thread's 4 px, row-invariant
    const int vx = 2 * x0 - 63;
    const int fx = vx >> 7;
    const float wx1base = (float)(vx & 127) * (1.0f / 128.0f);
    const int ebr = (fx + 1) * (GD * 3);

    // ---- stage both rows' fp16 y-interpolated planes ----
    #pragma unroll
    for (int e = tid; e < RPB * PLANE3; e += TPB) {
        const int c4 = e % 3;
        int q = e / 3;
        const int z  = q & (GD - 1);  q >>= 3;
        const int xi = q % NXS;
        const int r  = q / NXS;
        const int gx = min(max(xi - 1, 0), GW - 1);

        const int vy = 2 * (y0 + r) - 63;
        const int fy = vy >> 7;
        const float wy1 = (float)(vy & 127) * (1.0f / 128.0f);
        const float wy0 = 1.0f - wy1;
        const int cy0 = min(max(fy,     0), GH - 1);
        const int cy1 = min(max(fy + 1, 0), GH - 1);

        const float4* g0 = reinterpret_cast<const float4*>(grid)
            + (size_t)(((b * GH + cy0) * GW + gx) * GD + z) * 3 + c4;
        const float4* g1 = reinterpret_cast<const float4*>(grid)
            + (size_t)(((b * GH + cy1) * GW + gx) * GD + z) * 3 + c4;
        const float4 a  = __ldg(g0);
        const float4 bb = __ldg(g1);
        const __half2 h0 = __floats2half2_rn(wy0 * a.x + wy1 * bb.x,
                                             wy0 * a.y + wy1 * bb.y);
        const __half2 h1 = __floats2half2_rn(wy0 * a.z + wy1 * bb.z,
                                             wy0 * a.w + wy1 * bb.w);
        uint2 v;
        v.x = *(const unsigned*)&h0;
        v.y = *(const unsigned*)&h1;
        PY[e] = v;
    }
    __syncthreads();

    #pragma unroll
    for (int r = 0; r < RPB; r++) {
        const size_t rowpix = (size_t)(b * HH + y0 + r) * WW;
        const float4 g4 = __ldg(reinterpret_cast<const float4*>(guide + rowpix) + tid);
        const float4* ibase = reinterpret_cast<const float4*>(inp + rowpix * 3);
        const float4 ia = __ldg(ibase + tid * 3 + 0);
        const float4 ib = __ldg(ibase + tid * 3 + 1);
        const float4 ic = __ldg(ibase + tid * 3 + 2);

        const int ebase0 = r * PLANE3 + ebr;
        const int ebase1 = ebase0 + GD * 3;
        const float gin[4] = {g4.x, g4.y, g4.z, g4.w};
        float o[12];

        #pragma unroll
        for (int pp = 0; pp < 4; pp += 2) {
            // hoisted z-setup + weights for the pixel pair
            int e00[2], e01[2], e10[2], e11[2];
            __half2 W00[2], W01[2], W10[2], W11[2];
            #pragma unroll
            for (int q = 0; q < 2; q++) {
                const int p = pp + q;
                const float wx1 = wx1base + (float)p * (2.0f / 128.0f);
                const float wx0 = 1.0f - wx1;
                // tz in [-0.5, 7.5] -> iz in [-1, 7]: one-sided clamps
                const float tz = fmaf(gin[p], (float)GD, -0.5f);
                const int iz = __float2int_rd(tz);
                const float wz1 = tz - (float)iz;
                const float wz0 = 1.0f - wz1;
                const int z0 = max(iz, 0);
                const int z1 = min(iz + 1, GD - 1);
                e00[q] = ebase0 + z0 * 3;  e01[q] = ebase0 + z1 * 3;
                e10[q] = ebase1 + z0 * 3;  e11[q] = ebase1 + z1 * 3;
                W00[q] = __float2half2_rn(wx0 * wz0);
                W01[q] = __float2half2_rn(wx0 * wz1);
                W10[q] = __float2half2_rn(wx1 * wz0);
                W11[q] = __float2half2_rn(wx1 * wz1);
            }

            #pragma unroll
            for (int q = 0; q < 2; q++) {
                const int p = pp + q;

                // tree A: x0 taps (depth 2)
                const uint2 qa0 = PY[e00[q]], qa1 = PY[e00[q] + 1], qa2 = PY[e00[q] + 2];
                __half2 A0 = __hmul2(u2h(qa0.x), W00[q]);
                __half2 A1 = __hmul2(u2h(qa0.y), W00[q]);
                __half2 A2 = __hmul2(u2h(qa1.x), W00[q]);
                __half2 A3 = __hmul2(u2h(qa1.y), W00[q]);
                __half2 A4 = __hmul2(u2h(qa2.x), W00[q]);
                __half2 A5 = __hmul2(u2h(qa2.y), W00[q]);
                const uint2 qb0 = PY[e01[q]], qb1 = PY[e01[q] + 1], qb2 = PY[e01[q] + 2];
                A0 = __hfma2(u2h(qb0.x), W01[q], A0);
                A1 = __hfma2(u2h(qb0.y), W01[q], A1);
                A2 = __hfma2(u2h(qb1.x), W01[q], A2);
                A3 = __hfma2(u2h(qb1.y), W01[q], A3);
                A4 = __hfma2(u2h(qb2.x), W01[q], A4);
                A5 = __hfma2(u2h(qb2.y), W01[q], A5);

                // tree B: x1 taps (depth 2, independent)
                const uint2 qc0 = PY[e10[q]], qc1 = PY[e10[q] + 1], qc2 = PY[e10[q] + 2];
                __half2 B0 = __hmul2(u2h(qc0.x), W10[q]);
                __half2 B1 = __hmul2(u2h(qc0.y), W10[q]);
                __half2 B2 = __hmul2(u2h(qc1.x), W10[q]);
                __half2 B3 = __hmul2(u2h(qc1.y), W10[q]);
                __half2 B4 = __hmul2(u2h(qc2.x), W10[q]);
                __half2 B5 = __hmul2(u2h(qc2.y), W10[q]);
                const uint2 qd0 = PY[e11[q]], qd1 = PY[e11[q] + 1], qd2 = PY[e11[q] + 2];
                B0 = __hfma2(u2h(qd0.x), W11[q], B0);
                B1 = __hfma2(u2h(qd0.y), W11[q], B1);
                B2 = __hfma2(u2h(qd1.x), W11[q], B2);
                B3 = __hfma2(u2h(qd1.y), W11[q], B3);
                B4 = __hfma2(u2h(qd2.x), W11[q], B4);
                B5 = __hfma2(u2h(qd2.y), W11[q], B5);

                // merge trees
                const __half2 a0 = __hadd2(A0, B0);
                const __half2 a1 = __hadd2(A1, B1);
                const __half2 a2 = __hadd2(A2, B2);
                const __half2 a3 = __hadd2(A3, B3);
                const __half2 a4 = __hadd2(A4, B4);
                const __half2 a5 = __hadd2(A5, B5);

                const float c0 = __low2float(a0), c1 = __high2float(a0);
                const float c2 = __low2float(a1), c3 = __high2float(a1);
                const float c4 = __low2float(a2), c5 = __high2float(a2);
                const float c6 = __low2float(a3), c7 = __high2float(a3);
                const float c8 = __low2float(a4), c9 = __high2float(a4);
                const float cA = __low2float(a5), cB = __high2float(a5);

                float i0, i1, i2;
                if (p == 0)      { i0 = ia.x; i1 = ia.y; i2 = ia.z; }
                else if (p == 1) { i0 = ia.w; i1 = ib.x; i2 = ib.y; }
                else if (p == 2) { i0 = ib.z; i1 = ib.w; i2 = ic.x; }
                else             { i0 = ic.y; i1 = ic.z; i2 = ic.w; }

                o[3 * p + 0] = c0 * i0 + c1 * i1 + c2 * i2 + c3;
                o[3 * p + 1] = c4 * i0 + c5 * i1 + c6 * i2 + c7;
                o[3 * p + 2] = c8 * i0 + c9 * i1 + cA * i2 + cB;
            }
        }

        // batched epilogue stores for this row
        float4* obase = reinterpret_cast<float4*>(out + rowpix * 3);
        obase[tid * 3 + 0] = make_float4(o[0], o[1], o[2],  o[3]);
        obase[tid * 3 + 1] = make_float4(o[4], o[5], o[6],  o[7]);
        obase[tid * 3 + 2] = make_float4(o[8], o[9], o[10], o[11]);
    }
}

extern "C" void kernel_launch(void* const* d_in, const int* in_sizes, int n_in,
                              void* d_out, int out_size)
{
    const float* grid  = (const float*)d_in[0];
    const float* guide = (const float*)d_in[1];
    const float* inp   = (const float*)d_in[2];
    float* out = (float*)d_out;

    const int B = in_sizes[1] / (HH * WW);  // 4

    dim3 blk(TPB, 1, 1);
    dim3 grd(HH / RPB, B, 1);               // (512, 4)
    bsa_kernel<<<grd, blk>>>(grid, guide, inp, out);
}